// round 7
// baseline (speedup 1.0000x reference)
#include <cuda_runtime.h>
#include <math.h>

// Problem: B=2, S=2048, D=1024, N_COMPRESS=64, RANK=64, TOP_K=2
#define TOKENS 4096
#define DIM    1024
#define NEXP   64
#define RANK   64
#define CAP    8192
#define NSPLIT 2          // proj D-splits (512 d each)
#define DSPL   512
#define TILE_P 64         // picks per proj tile

#define OFF_IDX (TOKENS * RANK)
#define OFF_W   (TOKENS * RANK + TOKENS*2)

typedef unsigned long long ull;

__device__ __forceinline__ ull fma2(ull a, ull b, ull c) {
    ull d; asm("fma.rn.f32x2 %0, %1, %2, %3;" : "=l"(d) : "l"(a), "l"(b), "l"(c)); return d;
}
__device__ __forceinline__ float2 unpack2(ull v) {
    float2 r; asm("mov.b64 {%0, %1}, %2;" : "=f"(r.x), "=f"(r.y) : "l"(v)); return r;
}

// ---- scratch (device globals) ----
__device__ int   g_cnt[NEXP];
__device__ int   g_list[NEXP * CAP];
__device__ float g_w[TOKENS * 2];
__device__ float g_part[2 * TOKENS * NEXP];             // router partials (2 D-splits)
__device__ float g_scratch[NSPLIT * TOKENS * 2 * RANK]; // proj partials

// ============================================================
// Kernel 1: router partials. grid (64, 2), 256 thr.
// 64 tokens x 64 experts per block over 512 d. 4x4 k-packed f32x2.
// Two-stage prefetch pipeline; STS as float2 pairs (stride-34 rows
// are 8B-aligned, NOT 16B-aligned — float4 STS would fault).
// ============================================================
__global__ __launch_bounds__(256) void k_router(
    const float* __restrict__ x, const float* __restrict__ W)
{
    __shared__ __align__(16) float xs[2][64][34];
    __shared__ __align__(16) float ws[2][64][34];

    const int tid = threadIdx.x;
    if (blockIdx.x == 0 && blockIdx.y == 0 && tid < NEXP) g_cnt[tid] = 0;

    const int ty  = tid >> 4;
    const int tx  = tid & 15;
    const int tok0 = blockIdx.x * 64;
    const int d0   = blockIdx.y * 512;

    // per-thread load slots: 2 x-float4 + 2 w-float4
    const int lt0 = tid >> 3,         lc0 = tid & 7;          // idx = tid
    const int lt1 = (tid + 256) >> 3, lc1 = (tid + 256) & 7;  // idx = tid+256

    float4 px0, px1, pw0, pw1;
    #define R_LDG(dc) do { \
        px0 = *(const float4*)(x + (size_t)(tok0 + lt0) * DIM + d0 + (dc) + 4*lc0); \
        px1 = *(const float4*)(x + (size_t)(tok0 + lt1) * DIM + d0 + (dc) + 4*lc1); \
        pw0 = *(const float4*)(W + (size_t)lt0 * DIM + d0 + (dc) + 4*lc0); \
        pw1 = *(const float4*)(W + (size_t)lt1 * DIM + d0 + (dc) + 4*lc1); \
    } while (0)
    #define R_STS(bf) do { \
        *(float2*)&xs[bf][lt0][4*lc0]     = make_float2(px0.x, px0.y); \
        *(float2*)&xs[bf][lt0][4*lc0 + 2] = make_float2(px0.z, px0.w); \
        *(float2*)&xs[bf][lt1][4*lc1]     = make_float2(px1.x, px1.y); \
        *(float2*)&xs[bf][lt1][4*lc1 + 2] = make_float2(px1.z, px1.w); \
        *(float2*)&ws[bf][lt0][4*lc0]     = make_float2(pw0.x, pw0.y); \
        *(float2*)&ws[bf][lt0][4*lc0 + 2] = make_float2(pw0.z, pw0.w); \
        *(float2*)&ws[bf][lt1][4*lc1]     = make_float2(pw1.x, pw1.y); \
        *(float2*)&ws[bf][lt1][4*lc1 + 2] = make_float2(pw1.z, pw1.w); \
    } while (0)

    ull acc[4][4];
    #pragma unroll
    for (int i = 0; i < 4; i++)
        #pragma unroll
        for (int j = 0; j < 4; j++) acc[i][j] = 0ull;

    R_LDG(0);
    R_STS(0);
    __syncthreads();

    for (int ci = 0; ci < 16; ci++) {
        const int cur = ci & 1;
        if (ci < 15) R_LDG((ci + 1) * 32);

        #pragma unroll
        for (int k = 0; k < 32; k += 2) {
            ull a[4], b[4];
            #pragma unroll
            for (int i = 0; i < 4; i++) a[i] = *(const ull*)&xs[cur][ty + 16*i][k];
            #pragma unroll
            for (int j = 0; j < 4; j++) b[j] = *(const ull*)&ws[cur][tx + 16*j][k];
            #pragma unroll
            for (int i = 0; i < 4; i++)
                #pragma unroll
                for (int j = 0; j < 4; j++)
                    acc[i][j] = fma2(a[i], b[j], acc[i][j]);
        }

        if (ci < 15) R_STS(cur ^ 1);
        __syncthreads();
    }

    float* dst = g_part + (size_t)blockIdx.y * TOKENS * NEXP + (size_t)tok0 * NEXP;
    #pragma unroll
    for (int i = 0; i < 4; i++)
        #pragma unroll
        for (int j = 0; j < 4; j++) {
            float2 p = unpack2(acc[i][j]);
            dst[(ty + 16*i) * NEXP + tx + 16*j] = p.x + p.y;
        }
}

// ============================================================
// Kernel 2: combine 2 partials, top-2, softmax, outputs, scatter.
// ============================================================
__global__ __launch_bounds__(128) void k_top2(float* __restrict__ out, int out_size) {
    int t = blockIdx.x * blockDim.x + threadIdx.x;
    const float4* p0 = (const float4*)(g_part) + (size_t)t * 16;
    const float4* p1 = (const float4*)(g_part + (size_t)TOKENS * NEXP) + (size_t)t * 16;

    float m0 = -1e30f, m1 = -1e30f; int i0 = 0, i1 = 0;
    #pragma unroll
    for (int c = 0; c < 16; c++) {
        float4 a = p0[c], b = p1[c];
        float s[4] = { a.x + b.x, a.y + b.y, a.z + b.z, a.w + b.w };
        #pragma unroll
        for (int e = 0; e < 4; e++) {
            int n = 4*c + e;
            float v = s[e];
            if (v > m0)      { m1 = m0; i1 = i0; m0 = v; i0 = n; }
            else if (v > m1) { m1 = v; i1 = n; }
        }
    }
    float w0 = 1.0f / (1.0f + __expf(m1 - m0));
    float w1 = 1.0f - w0;

    g_w[t*2 + 0] = w0;
    g_w[t*2 + 1] = w1;
    if (out_size >= OFF_IDX + TOKENS*2) {
        out[OFF_IDX + t*2 + 0] = (float)i0;
        out[OFF_IDX + t*2 + 1] = (float)i1;
    }
    if (out_size >= OFF_W + TOKENS*2) {
        out[OFF_W + t*2 + 0] = w0;
        out[OFF_W + t*2 + 1] = w1;
    }
    int p = atomicAdd(&g_cnt[i0], 1);
    g_list[i0 * CAP + p] = t*2 + 0;
    p = atomicAdd(&g_cnt[i1], 1);
    g_list[i1 * CAP + p] = t*2 + 1;
}

// ============================================================
// Kernel 3: projection. 64 picks x 64 r per block, 256 threads,
// 4x4 k-packed f32x2, split-K x2, persistent blocks, in-kernel
// worklist. Two-stage prefetch pipeline (1 barrier per 32-d chunk).
// xsh stride 36 (144B = 16B-aligned rows -> float4 STS ok);
// nshT stride 34 with scalar transpose stores.
// ============================================================
__global__ __launch_bounds__(256) void k_proj(
    const float* __restrict__ x, const float* __restrict__ neurons)
{
    __shared__ __align__(16) float xsh[2][TILE_P][36];  // [buf][pick][k]
    __shared__ __align__(16) float nshT[2][RANK][34];   // [buf][r][k]
    __shared__ int psh[TILE_P];
    __shared__ int tsh[TILE_P];
    __shared__ int s_base[NEXP + 1];

    const int tid = threadIdx.x;
    const int ty = tid >> 4;
    const int tx = tid & 15;

    // load-slot geometry (idx = tid and tid+256 over 512 float4 each)
    const int xp0 = tid >> 3,         xc0 = tid & 7;
    const int xp1 = (tid + 256) >> 3, xc1 = (tid + 256) & 7;
    const int nd0 = tid >> 4,         nr0 = tid & 15;
    const int nd1 = (tid + 256) >> 4, nr1 = (tid + 256) & 15;

    if (tid == 0) {
        int sum = 0;
        #pragma unroll
        for (int e = 0; e < NEXP; e++) {
            s_base[e] = sum;
            sum += (g_cnt[e] + TILE_P - 1) >> 6;
        }
        s_base[NEXP] = sum;
    }
    __syncthreads();
    const int nwork = s_base[NEXP] * NSPLIT;

    for (int w = blockIdx.x; w < nwork; w += gridDim.x) {
        const int it = w >> 1;
        const int sp = w & 1;
        int e = 0;
        while (s_base[e + 1] <= it) e++;
        const int off = (it - s_base[e]) * TILE_P;
        int cnt = g_cnt[e] - off;
        if (cnt > TILE_P) cnt = TILE_P;

        if (tid < TILE_P) {
            if (tid < cnt) {
                int p = g_list[e * CAP + off + tid];
                psh[tid] = p;
                tsh[tid] = p >> 1;
            } else {
                psh[tid] = -1;
                tsh[tid] = -1;
            }
        }
        __syncthreads();

        const float* nb = neurons + ((size_t)e * DIM + (size_t)sp * DSPL) * RANK;
        const float* xb = x + sp * DSPL;
        const int tok0 = tsh[xp0];
        const int tok1 = tsh[xp1];

        float4 qx0, qx1, qn0, qn1;
        #define P_LDG(dc) do { \
            qx0 = make_float4(0.f,0.f,0.f,0.f); \
            qx1 = make_float4(0.f,0.f,0.f,0.f); \
            if (tok0 >= 0) qx0 = *(const float4*)(xb + (size_t)tok0 * DIM + (dc) + 4*xc0); \
            if (tok1 >= 0) qx1 = *(const float4*)(xb + (size_t)tok1 * DIM + (dc) + 4*xc1); \
            qn0 = *(const float4*)(nb + (size_t)((dc) + nd0) * RANK + nr0 * 4); \
            qn1 = *(const float4*)(nb + (size_t)((dc) + nd1) * RANK + nr1 * 4); \
        } while (0)
        #define P_STS(bf) do { \
            *(float4*)&xsh[bf][xp0][4*xc0] = qx0; \
            *(float4*)&xsh[bf][xp1][4*xc1] = qx1; \
            nshT[bf][4*nr0+0][nd0] = qn0.x; nshT[bf][4*nr0+1][nd0] = qn0.y; \
            nshT[bf][4*nr0+2][nd0] = qn0.z; nshT[bf][4*nr0+3][nd0] = qn0.w; \
            nshT[bf][4*nr1+0][nd1] = qn1.x; nshT[bf][4*nr1+1][nd1] = qn1.y; \
            nshT[bf][4*nr1+2][nd1] = qn1.z; nshT[bf][4*nr1+3][nd1] = qn1.w; \
        } while (0)

        ull acc[4][4];
        #pragma unroll
        for (int i = 0; i < 4; i++)
            #pragma unroll
            for (int j = 0; j < 4; j++) acc[i][j] = 0ull;

        P_LDG(0);
        P_STS(0);
        __syncthreads();

        for (int ci = 0; ci < DSPL / 32; ci++) {
            const int cur = ci & 1;
            if (ci < DSPL / 32 - 1) P_LDG((ci + 1) * 32);

            #pragma unroll
            for (int k = 0; k < 32; k += 2) {
                ull a[4], b[4];
                #pragma unroll
                for (int i = 0; i < 4; i++) a[i] = *(const ull*)&xsh[cur][ty + 16*i][k];
                #pragma unroll
                for (int j = 0; j < 4; j++) b[j] = *(const ull*)&nshT[cur][tx + 16*j][k];
                #pragma unroll
                for (int i = 0; i < 4; i++)
                    #pragma unroll
                    for (int j = 0; j < 4; j++)
                        acc[i][j] = fma2(a[i], b[j], acc[i][j]);
            }

            if (ci < DSPL / 32 - 1) P_STS(cur ^ 1);
            __syncthreads();
        }

        // epilogue: disjoint (split, pick) scratch rows
        float* sb = g_scratch + (size_t)sp * (TOKENS * 2) * RANK;
        #pragma unroll
        for (int i = 0; i < 4; i++) {
            int p = psh[ty + 16*i];
            if (p >= 0) {
                #pragma unroll
                for (int j = 0; j < 4; j++) {
                    float2 v = unpack2(acc[i][j]);
                    sb[(size_t)p * RANK + tx + 16*j] = v.x + v.y;
                }
            }
        }
        __syncthreads();
    }
}

// ============================================================
// Kernel 4: deterministic reduce: out[t,r] = sum_k w_k * sum_s part
// ============================================================
__global__ __launch_bounds__(256) void k_reduce(float* __restrict__ out) {
    int i = blockIdx.x * blockDim.x + threadIdx.x;
    int t = i >> 4;
    int c = (i & 15) * 4;
    float4 acc = make_float4(0.f, 0.f, 0.f, 0.f);
    #pragma unroll
    for (int k = 0; k < 2; k++) {
        int p = t*2 + k;
        float w = g_w[p];
        #pragma unroll
        for (int s = 0; s < NSPLIT; s++) {
            float4 v = *(const float4*)&g_scratch[((size_t)s * (TOKENS*2) + p) * RANK + c];
            acc.x += w * v.x; acc.y += w * v.y; acc.z += w * v.z; acc.w += w * v.w;
        }
    }
    *(float4*)&out[(size_t)t * RANK + c] = acc;
}

// ============================================================
extern "C" void kernel_launch(void* const* d_in, const int* in_sizes, int n_in,
                              void* d_out, int out_size) {
    const float* x       = (const float*)d_in[0];
    const float* router  = (const float*)d_in[1];
    const float* neurons = (const float*)d_in[2];
    float* out = (float*)d_out;

    k_router<<<dim3(TOKENS/64, 2), 256>>>(x, router);
    k_top2<<<TOKENS/128, 128>>>(out, out_size);
    k_proj<<<592, 256>>>(x, neurons);
    k_reduce<<<TOKENS*RANK/4/256, 256>>>(out);
}

// round 8
// speedup vs baseline: 1.1024x; 1.1024x over previous
#include <cuda_runtime.h>
#include <math.h>

// Problem: B=2, S=2048, D=1024, N_COMPRESS=64, RANK=64, TOP_K=2
#define TOKENS 4096
#define DIM    1024
#define NEXP   64
#define RANK   64
#define CAP    8192
#define NSPLIT 4          // proj D-splits (256 d each)
#define DSPL   256
#define TILE_P 128        // picks per proj tile

#define OFF_IDX (TOKENS * RANK)
#define OFF_W   (TOKENS * RANK + TOKENS*2)

typedef unsigned long long ull;

__device__ __forceinline__ ull fma2(ull a, ull b, ull c) {
    ull d; asm("fma.rn.f32x2 %0, %1, %2, %3;" : "=l"(d) : "l"(a), "l"(b), "l"(c)); return d;
}
__device__ __forceinline__ float2 unpack2(ull v) {
    float2 r; asm("mov.b64 {%0, %1}, %2;" : "=f"(r.x), "=f"(r.y) : "l"(v)); return r;
}

// ---- scratch (device globals) ----
__device__ int   g_cnt[NEXP];
__device__ int   g_list[NEXP * CAP];
__device__ float g_w[TOKENS * 2];
__device__ float g_part[2 * TOKENS * NEXP];             // router partials (2 D-splits)
__device__ float g_scratch[NSPLIT * TOKENS * 2 * RANK]; // proj partials

// ============================================================
// Kernel 1: router partials. grid (64, 2), 256 thr (R4 structure).
// 64 tokens x 64 experts per block over 512 d. 4x4 k-packed f32x2.
// a-operand via LDS.128 (xs stride 36 = 16B-aligned rows);
// b-operand via LDS.64 (ws stride 34 = conflict-free banks 2*tx).
// ============================================================
__global__ __launch_bounds__(256) void k_router(
    const float* __restrict__ x, const float* __restrict__ W)
{
    __shared__ __align__(16) float xs[64][36];
    __shared__ __align__(16) float ws[64][34];

    const int tid = threadIdx.x;
    if (blockIdx.x == 0 && blockIdx.y == 0 && tid < NEXP) g_cnt[tid] = 0;

    const int ty  = tid >> 4;
    const int tx  = tid & 15;
    const int tok0 = blockIdx.x * 64;
    const int d0   = blockIdx.y * 512;

    ull acc[4][4];
    #pragma unroll
    for (int i = 0; i < 4; i++)
        #pragma unroll
        for (int j = 0; j < 4; j++) acc[i][j] = 0ull;

    for (int dc = 0; dc < 512; dc += 32) {
        #pragma unroll
        for (int r = 0; r < 2; r++) {
            int idx = tid + r * 256;
            int t = idx >> 3, c = idx & 7;
            float4 v = *(const float4*)(x + (size_t)(tok0 + t) * DIM + d0 + dc + 4 * c);
            *(float4*)&xs[t][4*c] = v;   // stride 36: rows 144B, 16B-aligned
            float4 u = *(const float4*)(W + (size_t)t * DIM + d0 + dc + 4 * c);
            ws[t][4*c+0] = u.x; ws[t][4*c+1] = u.y; ws[t][4*c+2] = u.z; ws[t][4*c+3] = u.w;
        }
        __syncthreads();

        #pragma unroll
        for (int k = 0; k < 32; k += 4) {
            ulonglong2 a[4];
            #pragma unroll
            for (int i = 0; i < 4; i++)
                a[i] = *(const ulonglong2*)&xs[ty + 16*i][k];   // LDS.128: (k,k+1),(k+2,k+3)
            #pragma unroll
            for (int h = 0; h < 2; h++) {
                ull b[4];
                #pragma unroll
                for (int j = 0; j < 4; j++) b[j] = *(const ull*)&ws[tx + 16*j][k + 2*h];
                #pragma unroll
                for (int i = 0; i < 4; i++) {
                    ull av = h ? a[i].y : a[i].x;
                    #pragma unroll
                    for (int j = 0; j < 4; j++)
                        acc[i][j] = fma2(av, b[j], acc[i][j]);
                }
            }
        }
        __syncthreads();
    }

    float* dst = g_part + (size_t)blockIdx.y * TOKENS * NEXP + (size_t)tok0 * NEXP;
    #pragma unroll
    for (int i = 0; i < 4; i++)
        #pragma unroll
        for (int j = 0; j < 4; j++) {
            float2 p = unpack2(acc[i][j]);
            dst[(ty + 16*i) * NEXP + tx + 16*j] = p.x + p.y;
        }
}

// ============================================================
// Kernel 2: combine 2 partials, top-2, softmax, outputs, scatter.
// ============================================================
__global__ __launch_bounds__(128) void k_top2(float* __restrict__ out, int out_size) {
    int t = blockIdx.x * blockDim.x + threadIdx.x;
    const float4* p0 = (const float4*)(g_part) + (size_t)t * 16;
    const float4* p1 = (const float4*)(g_part + (size_t)TOKENS * NEXP) + (size_t)t * 16;

    float m0 = -1e30f, m1 = -1e30f; int i0 = 0, i1 = 0;
    #pragma unroll
    for (int c = 0; c < 16; c++) {
        float4 a = p0[c], b = p1[c];
        float s[4] = { a.x + b.x, a.y + b.y, a.z + b.z, a.w + b.w };
        #pragma unroll
        for (int e = 0; e < 4; e++) {
            int n = 4*c + e;
            float v = s[e];
            if (v > m0)      { m1 = m0; i1 = i0; m0 = v; i0 = n; }
            else if (v > m1) { m1 = v; i1 = n; }
        }
    }
    float w0 = 1.0f / (1.0f + __expf(m1 - m0));
    float w1 = 1.0f - w0;

    g_w[t*2 + 0] = w0;
    g_w[t*2 + 1] = w1;
    if (out_size >= OFF_IDX + TOKENS*2) {
        out[OFF_IDX + t*2 + 0] = (float)i0;
        out[OFF_IDX + t*2 + 1] = (float)i1;
    }
    if (out_size >= OFF_W + TOKENS*2) {
        out[OFF_W + t*2 + 0] = w0;
        out[OFF_W + t*2 + 1] = w1;
    }
    int p = atomicAdd(&g_cnt[i0], 1);
    g_list[i0 * CAP + p] = t*2 + 0;
    p = atomicAdd(&g_cnt[i1], 1);
    g_list[i1 * CAP + p] = t*2 + 1;
}

// ============================================================
// Kernel 3: projection (R4 structure). 128 picks x 64 r per block,
// 256 threads, 8x4 k-packed f32x2, split-K x4, persistent blocks,
// in-kernel worklist. a via LDS.128 (xsh stride 36), b via LDS.64
// (nshT stride 34, conflict-free).
// ============================================================
__global__ __launch_bounds__(256, 2) void k_proj(
    const float* __restrict__ x, const float* __restrict__ neurons)
{
    __shared__ __align__(16) float xsh[TILE_P][36];  // [pick][k]
    __shared__ __align__(16) float nshT[RANK][34];   // [r][k]
    __shared__ int psh[TILE_P];
    __shared__ int tsh[TILE_P];
    __shared__ int s_nt[NEXP];
    __shared__ int s_base[NEXP + 1];

    const int tid = threadIdx.x;
    const int ty = tid >> 4;   // 0..15 -> 8 pick rows (ty + 16*i)
    const int tx = tid & 15;   // 0..15 -> 4 r cols (tx + 16*j)

    if (tid < NEXP) s_nt[tid] = (g_cnt[tid] + TILE_P - 1) >> 7;
    __syncthreads();
    if (tid == 0) {
        int sum = 0;
        #pragma unroll
        for (int e = 0; e < NEXP; e++) { s_base[e] = sum; sum += s_nt[e]; }
        s_base[NEXP] = sum;
    }
    __syncthreads();
    const int nwork = s_base[NEXP] * NSPLIT;

    for (int w = blockIdx.x; w < nwork; w += gridDim.x) {
        const int it = w >> 2;
        const int sp = w & 3;
        int e = 0;
        while (s_base[e + 1] <= it) e++;
        const int off = (it - s_base[e]) * TILE_P;
        int cnt = g_cnt[e] - off;
        if (cnt > TILE_P) cnt = TILE_P;

        if (tid < TILE_P) {
            if (tid < cnt) {
                int p = g_list[e * CAP + off + tid];
                psh[tid] = p;
                tsh[tid] = p >> 1;
            } else {
                psh[tid] = -1;
                tsh[tid] = -1;
            }
        }
        __syncthreads();

        ull acc[8][4];
        #pragma unroll
        for (int i = 0; i < 8; i++)
            #pragma unroll
            for (int j = 0; j < 4; j++) acc[i][j] = 0ull;

        const float* nb = neurons + ((size_t)e * DIM + (size_t)sp * DSPL) * RANK;
        const int dbase = sp * DSPL;

        for (int dc = 0; dc < DSPL; dc += 32) {
            // gathered x: 128 pick rows x 32 d (d-contig: direct copy)
            #pragma unroll
            for (int s = 0; s < 4; s++) {
                int idx = tid + 256 * s;        // 0..1023
                int pr = idx >> 3, c = idx & 7;
                int tok = tsh[pr];
                float4 v = make_float4(0.f, 0.f, 0.f, 0.f);
                if (tok >= 0)
                    v = *(const float4*)(x + (size_t)tok * DIM + dbase + dc + 4 * c);
                *(float4*)&xsh[pr][4*c] = v;
            }
            // neurons [32 d][64 r] -> transposed nshT[r][d]
            #pragma unroll
            for (int s = 0; s < 2; s++) {
                int idx = tid + 256 * s;        // 0..511
                int d = idx >> 4, rc = idx & 15;
                float4 v = *(const float4*)(nb + (size_t)(dc + d) * RANK + rc * 4);
                nshT[4*rc+0][d] = v.x;
                nshT[4*rc+1][d] = v.y;
                nshT[4*rc+2][d] = v.z;
                nshT[4*rc+3][d] = v.w;
            }
            __syncthreads();

            #pragma unroll
            for (int k = 0; k < 32; k += 4) {
                ulonglong2 a[8];
                #pragma unroll
                for (int i = 0; i < 8; i++)
                    a[i] = *(const ulonglong2*)&xsh[ty + 16*i][k];   // LDS.128
                #pragma unroll
                for (int h = 0; h < 2; h++) {
                    ull b[4];
                    #pragma unroll
                    for (int j = 0; j < 4; j++) b[j] = *(const ull*)&nshT[tx + 16*j][k + 2*h];
                    #pragma unroll
                    for (int i = 0; i < 8; i++) {
                        ull av = h ? a[i].y : a[i].x;
                        #pragma unroll
                        for (int j = 0; j < 4; j++)
                            acc[i][j] = fma2(av, b[j], acc[i][j]);
                    }
                }
            }
            __syncthreads();
        }

        // epilogue: disjoint (split, pick) scratch rows
        float* sb = g_scratch + (size_t)sp * (TOKENS * 2) * RANK;
        #pragma unroll
        for (int i = 0; i < 8; i++) {
            int p = psh[ty + 16*i];
            if (p >= 0) {
                #pragma unroll
                for (int j = 0; j < 4; j++) {
                    float2 v = unpack2(acc[i][j]);
                    sb[(size_t)p * RANK + tx + 16*j] = v.x + v.y;
                }
            }
        }
        __syncthreads();
    }
}

// ============================================================
// Kernel 4: deterministic reduce: out[t,r] = sum_k w_k * sum_s part
// ============================================================
__global__ __launch_bounds__(256) void k_reduce(float* __restrict__ out) {
    int i = blockIdx.x * blockDim.x + threadIdx.x;
    int t = i >> 4;
    int c = (i & 15) * 4;
    float4 acc = make_float4(0.f, 0.f, 0.f, 0.f);
    #pragma unroll
    for (int k = 0; k < 2; k++) {
        int p = t*2 + k;
        float w = g_w[p];
        #pragma unroll
        for (int s = 0; s < NSPLIT; s++) {
            float4 v = *(const float4*)&g_scratch[((size_t)s * (TOKENS*2) + p) * RANK + c];
            acc.x += w * v.x; acc.y += w * v.y; acc.z += w * v.z; acc.w += w * v.w;
        }
    }
    *(float4*)&out[(size_t)t * RANK + c] = acc;
}

// ============================================================
extern "C" void kernel_launch(void* const* d_in, const int* in_sizes, int n_in,
                              void* d_out, int out_size) {
    const float* x       = (const float*)d_in[0];
    const float* router  = (const float*)d_in[1];
    const float* neurons = (const float*)d_in[2];
    float* out = (float*)d_out;

    k_router<<<dim3(TOKENS/64, 2), 256>>>(x, router);
    k_top2<<<TOKENS/128, 128>>>(out, out_size);
    k_proj<<<296, 256>>>(x, neurons);
    k_reduce<<<TOKENS*RANK/4/256, 256>>>(out);
}